// round 14
// baseline (speedup 1.0000x reference)
#include <cuda_runtime.h>
#include <cuda_bf16.h>
#include <cstdint>

#define SEQ  2048
#define DM   1024
#define NH   16
#define HD   64
#define NB   2
#define MROWS (NB*SEQ)

// ---------------- scratch (device globals; no allocation allowed) ----------
#define NX   ((size_t)MROWS*DM)
#define NW   ((size_t)3*DM*DM)
#define NPW  ((size_t)DM*DM)
#define NQKV ((size_t)NB*NH*SEQ*HD)

__device__ __nv_bfloat16 g_xh[NX],  g_xl[NX];
__device__ __nv_bfloat16 g_wh[NW],  g_wl[NW];
__device__ __nv_bfloat16 g_pwh[NPW], g_pwl[NPW];
__device__ __nv_bfloat16 g_ah[NX],  g_al[NX];
__device__ __nv_bfloat16 g_qh[NQKV], g_ql[NQKV];
__device__ __nv_bfloat16 g_kh[NQKV], g_kl[NQKV];
__device__ __nv_bfloat16 g_vh[NQKV], g_vl[NQKV];

// ---------------- PTX helpers ----------------------------------------------
__device__ __forceinline__ uint32_t smem_u32(const void* p) {
    uint32_t a;
    asm("{ .reg .u64 t; cvta.to.shared.u64 t, %1; cvt.u32.u64 %0, t; }"
        : "=r"(a) : "l"(p));
    return a;
}
#define CP16(s, g) \
    asm volatile("cp.async.cg.shared.global [%0], [%1], 16;" :: "r"(s), "l"(g))
#define CP_COMMIT() asm volatile("cp.async.commit_group;" ::: "memory")
#define CP_WAIT1()  asm volatile("cp.async.wait_group 1;" ::: "memory")
#define CP_WAIT0()  asm volatile("cp.async.wait_group 0;" ::: "memory")

__device__ __forceinline__ uint32_t sw128(uint32_t off) {
    return off ^ ((off >> 3) & 0x70);
}
__device__ __forceinline__ void ldm_x4(uint32_t* r, uint32_t a) {
    asm("ldmatrix.sync.aligned.m8n8.x4.shared.b16 {%0,%1,%2,%3}, [%4];"
        : "=r"(r[0]), "=r"(r[1]), "=r"(r[2]), "=r"(r[3]) : "r"(a));
}
__device__ __forceinline__ void ldm_x4t(uint32_t* r, uint32_t a) {
    asm("ldmatrix.sync.aligned.m8n8.x4.trans.shared.b16 {%0,%1,%2,%3}, [%4];"
        : "=r"(r[0]), "=r"(r[1]), "=r"(r[2]), "=r"(r[3]) : "r"(a));
}
__device__ __forceinline__ void mma_bf16(float* c, const uint32_t* a,
                                         const uint32_t* b) {
    asm("mma.sync.aligned.m16n8k16.row.col.f32.bf16.bf16.f32 "
        "{%0,%1,%2,%3}, {%4,%5,%6,%7}, {%8,%9}, {%0,%1,%2,%3};"
        : "+f"(c[0]), "+f"(c[1]), "+f"(c[2]), "+f"(c[3])
        : "r"(a[0]), "r"(a[1]), "r"(a[2]), "r"(a[3]), "r"(b[0]), "r"(b[1]));
}
__device__ __forceinline__ uint32_t cvt2(float hi, float lo) {
    uint32_t r;
    asm("cvt.rn.bf16x2.f32 %0, %1, %2;" : "=r"(r) : "f"(hi), "f"(lo));
    return r;
}

// ---------------- fused fp32 -> bf16 hi/lo split (x, qkv_w, proj_w) --------
__global__ void __launch_bounds__(256)
split_all(const float* __restrict__ x, const float* __restrict__ w,
          const float* __restrict__ pw)
{
    const size_t i = ((size_t)blockIdx.x * 256 + threadIdx.x) * 4;
    const float* src;
    __nv_bfloat16 *hi, *lo;
    size_t off;
    if (i < NX)           { src = x;  hi = g_xh;  lo = g_xl;  off = i; }
    else if (i < NX + NW) { src = w;  hi = g_wh;  lo = g_wl;  off = i - NX; }
    else                  { src = pw; hi = g_pwh; lo = g_pwl; off = i - NX - NW; }
    float4 v = *(const float4*)(src + off);
    float f[4] = {v.x, v.y, v.z, v.w};
    __nv_bfloat16 h4[4], l4[4];
#pragma unroll
    for (int j = 0; j < 4; j++) {
        h4[j] = __float2bfloat16(f[j]);
        l4[j] = __float2bfloat16(f[j] - __bfloat162float(h4[j]));
    }
    *(uint2*)(hi + off) = *(uint2*)h4;
    *(uint2*)(lo + off) = *(uint2*)l4;
}

// ---------------------------------------------------------------------------
// QKV GEMM: CTA 128x96, 128 thr (2m x 2n warps), warp 64x48, BK=32,
// 2-stage (56 KB), carveout 100 (round-12 winning config).
// ---------------------------------------------------------------------------
#define GSTG 28672   // A 16KB + W 12KB

__global__ void __launch_bounds__(128, 3)
gemm_qkv(const __nv_bfloat16* __restrict__ Ah, const __nv_bfloat16* __restrict__ Al,
         const __nv_bfloat16* __restrict__ Wh, const __nv_bfloat16* __restrict__ Wl,
         const float* __restrict__ bias)
{
    constexpr int K = 1024, KT = K / 32;
    extern __shared__ char dsm[];
    const uint32_t smb = smem_u32(dsm);

    const int tid = threadIdx.x, lane = tid & 31, wid = tid >> 5;
    const int wm = wid & 1, wn = wid >> 1;
    const int bn = blockIdx.x * 96, bm = blockIdx.y * 128;

    auto load_stage = [&](int s, int kt) {
        const uint32_t base = smb + s * GSTG;
#pragma unroll
        for (int i = 0; i < 8; i++) {
            int idx = tid + i * 128;
            int r = idx >> 3, c = idx & 7;
            const __nv_bfloat16* g = ((c < 4) ? Ah : Al)
                + (size_t)(bm + r) * K + kt * 32 + (c & 3) * 8;
            CP16(base + sw128(r * 128 + c * 16), g);
        }
#pragma unroll
        for (int i = 0; i < 6; i++) {
            int idx = tid + i * 128;
            int r = idx >> 3, c = idx & 7;
            const __nv_bfloat16* g = ((c < 4) ? Wh : Wl)
                + (size_t)(bn + r) * K + kt * 32 + (c & 3) * 8;
            CP16(base + 16384 + sw128(r * 128 + c * 16), g);
        }
        CP_COMMIT();
    };

    float acc[4][6][4];
#pragma unroll
    for (int mt = 0; mt < 4; mt++)
#pragma unroll
        for (int nt = 0; nt < 6; nt++)
#pragma unroll
            for (int j = 0; j < 4; j++) acc[mt][nt][j] = 0.f;

    const int a_row = wm * 64 + (lane & 15);
    const int a_kb  = (lane >> 4) * 16;
    const int b_row = wn * 48 + (lane & 7) + ((lane >> 4) << 3);
    const int b_kb  = ((lane >> 3) & 1) * 16;

    load_stage(0, 0);
    load_stage(1, 1);

    for (int t = 0; t < KT; t++) {
        const int s = t & 1;
        if (t == KT - 1) { CP_WAIT0(); } else { CP_WAIT1(); }
        __syncthreads();

        const uint32_t bA = smb + s * GSTG;
        const uint32_t bW = bA + 16384;
#pragma unroll
        for (int ks = 0; ks < 2; ks++) {
            uint32_t afh[4][4], afl[4][4];
#pragma unroll
            for (int mt = 0; mt < 4; mt++) {
                const uint32_t off = (a_row + mt * 16) * 128 + a_kb + ks * 32;
                ldm_x4(afh[mt], bA + sw128(off));
                ldm_x4(afl[mt], bA + sw128(off + 64));
            }
#pragma unroll
            for (int ng = 0; ng < 3; ng++) {
                uint32_t bfh[4], bfl[4];
                const uint32_t off = (b_row + ng * 16) * 128 + b_kb + ks * 32;
                ldm_x4(bfh, bW + sw128(off));
                ldm_x4(bfl, bW + sw128(off + 64));
#pragma unroll
                for (int mt = 0; mt < 4; mt++) {
                    mma_bf16(acc[mt][2*ng],   afh[mt], &bfh[0]);
                    mma_bf16(acc[mt][2*ng],   afh[mt], &bfl[0]);
                    mma_bf16(acc[mt][2*ng],   afl[mt], &bfh[0]);
                    mma_bf16(acc[mt][2*ng+1], afh[mt], &bfh[2]);
                    mma_bf16(acc[mt][2*ng+1], afh[mt], &bfl[2]);
                    mma_bf16(acc[mt][2*ng+1], afl[mt], &bfh[2]);
                }
            }
        }
        __syncthreads();
        if (t + 2 < KT) load_stage(s, t + 2);
    }

    const int gr = lane >> 2, gc = (lane & 3) * 2;
#pragma unroll
    for (int mt = 0; mt < 4; mt++) {
#pragma unroll
        for (int half = 0; half < 2; half++) {
            const int m = bm + wm * 64 + mt * 16 + gr + half * 8;
#pragma unroll
            for (int nt = 0; nt < 6; nt++) {
                const int n = bn + wn * 48 + nt * 8 + gc;
                float vx = acc[mt][nt][half * 2 + 0] + __ldg(bias + n);
                float vy = acc[mt][nt][half * 2 + 1] + __ldg(bias + n + 1);
                const int chunk = n >> 10, rem = n & 1023;
                const int h = rem >> 6, d = rem & 63;
                const int b = m >> 11, tt = m & 2047;
                if (chunk == 0) { vx *= 0.125f; vy *= 0.125f; }
                __nv_bfloat16 hx = __float2bfloat16(vx);
                __nv_bfloat16 hy = __float2bfloat16(vy);
                __nv_bfloat16 lx = __float2bfloat16(vx - __bfloat162float(hx));
                __nv_bfloat16 ly = __float2bfloat16(vy - __bfloat162float(hy));
                __nv_bfloat16* dh = (chunk == 0) ? g_qh : (chunk == 1) ? g_kh : g_vh;
                __nv_bfloat16* dl = (chunk == 0) ? g_ql : (chunk == 1) ? g_kl : g_vl;
                const size_t off = (((size_t)b * NH + h) * SEQ + tt) * HD + d;
                __nv_bfloat162 ph; ph.x = hx; ph.y = hy;
                __nv_bfloat162 pl; pl.x = lx; pl.y = ly;
                *(__nv_bfloat162*)&dh[off] = ph;
                *(__nv_bfloat162*)&dl[off] = pl;
            }
        }
    }
}

// ---------------------------------------------------------------------------
// Projection GEMM (round-10 config): CTA 128x256, 8 warps (2m x 4n),
// warp 64x64, BK=64, 2-stage (192 KB).
// ---------------------------------------------------------------------------
#define A_T 16384
#define W_T 32768
#define STAGE_B (2*A_T + 2*W_T)    // 98304

__global__ void __launch_bounds__(256)
gemm_proj(const __nv_bfloat16* __restrict__ Ah, const __nv_bfloat16* __restrict__ Al,
          const __nv_bfloat16* __restrict__ Wh, const __nv_bfloat16* __restrict__ Wl,
          const float* __restrict__ bias, float* __restrict__ C)
{
    constexpr int K = 1024, KT = K / 64, N = DM;
    extern __shared__ char dsm[];
    const uint32_t smb = smem_u32(dsm);

    const int tid = threadIdx.x, lane = tid & 31, wid = tid >> 5;
    const int wm = wid & 1, wn = wid >> 1;
    const int bn = blockIdx.x * 256, bm = blockIdx.y * 128;

    const __nv_bfloat16* gA[2] = {Ah + (size_t)bm * K, Al + (size_t)bm * K};
    const __nv_bfloat16* gW[2] = {Wh + (size_t)bn * K, Wl + (size_t)bn * K};

    auto load_stage = [&](int s, int kt) {
        const uint32_t base = smb + s * STAGE_B;
#pragma unroll
        for (int h = 0; h < 2; h++) {
            const uint32_t tb = base + h * A_T;
            const __nv_bfloat16* g = gA[h] + (size_t)kt * 64;
#pragma unroll
            for (int i = 0; i < 4; i++) {
                int idx = tid + i * 256;
                int r = idx >> 3, seg = idx & 7;
                CP16(tb + sw128(r * 128 + seg * 16), g + (size_t)r * K + seg * 8);
            }
        }
#pragma unroll
        for (int h = 0; h < 2; h++) {
            const uint32_t tb = base + 2 * A_T + h * W_T;
            const __nv_bfloat16* g = gW[h] + (size_t)kt * 64;
#pragma unroll
            for (int i = 0; i < 8; i++) {
                int idx = tid + i * 256;
                int r = idx >> 3, seg = idx & 7;
                CP16(tb + sw128(r * 128 + seg * 16), g + (size_t)r * K + seg * 8);
            }
        }
        CP_COMMIT();
    };

    float acc[4][8][4];
#pragma unroll
    for (int mt = 0; mt < 4; mt++)
#pragma unroll
        for (int nt = 0; nt < 8; nt++)
#pragma unroll
            for (int j = 0; j < 4; j++) acc[mt][nt][j] = 0.f;

    const int a_row = wm * 64 + (lane & 15);
    const int a_kb  = (lane >> 4) * 16;
    const int b_row = wn * 64 + (lane & 7) + ((lane >> 4) << 3);
    const int b_kb  = ((lane >> 3) & 1) * 16;

    load_stage(0, 0);
    load_stage(1, 1);

    for (int t = 0; t < KT; t++) {
        const int s = t & 1;
        if (t == KT - 1) { CP_WAIT0(); } else { CP_WAIT1(); }
        __syncthreads();

        const uint32_t bAh = smb + s * STAGE_B;
        const uint32_t bAl = bAh + A_T;
        const uint32_t bWh = bAh + 2 * A_T;
        const uint32_t bWl = bWh + W_T;

#pragma unroll
        for (int ks = 0; ks < 4; ks++) {
            uint32_t afh[4][4], afl[4][4];
#pragma unroll
            for (int mt = 0; mt < 4; mt++) {
                const uint32_t off = sw128((a_row + mt * 16) * 128 + a_kb + ks * 32);
                ldm_x4(afh[mt], bAh + off);
                ldm_x4(afl[mt], bAl + off);
            }
#pragma unroll
            for (int ng = 0; ng < 4; ng++) {
                uint32_t bfh[4], bfl[4];
                const uint32_t off = sw128((b_row + ng * 16) * 128 + b_kb + ks * 32);
                ldm_x4(bfh, bWh + off);
                ldm_x4(bfl, bWl + off);
#pragma unroll
                for (int mt = 0; mt < 4; mt++) {
                    mma_bf16(acc[mt][2*ng],   afh[mt], &bfh[0]);
                    mma_bf16(acc[mt][2*ng],   afh[mt], &bfl[0]);
                    mma_bf16(acc[mt][2*ng],   afl[mt], &bfh[0]);
                    mma_bf16(acc[mt][2*ng+1], afh[mt], &bfh[2]);
                    mma_bf16(acc[mt][2*ng+1], afh[mt], &bfl[2]);
                    mma_bf16(acc[mt][2*ng+1], afl[mt], &bfh[2]);
                }
            }
        }
        __syncthreads();
        if (t + 2 < KT) load_stage(s, t + 2);
    }

    const int gr = lane >> 2, gc = (lane & 3) * 2;
#pragma unroll
    for (int mt = 0; mt < 4; mt++) {
#pragma unroll
        for (int half = 0; half < 2; half++) {
            const int m = bm + wm * 64 + mt * 16 + gr + half * 8;
#pragma unroll
            for (int nt = 0; nt < 8; nt++) {
                const int n = bn + wn * 64 + nt * 8 + gc;
                float2 v;
                v.x = acc[mt][nt][half * 2 + 0] + __ldg(bias + n);
                v.y = acc[mt][nt][half * 2 + 1] + __ldg(bias + n + 1);
                *(float2*)&C[(size_t)m * N + n] = v;
            }
        }
    }
}

// ---------------------------------------------------------------------------
// mma.sync flash attention — round-12 config + Q FRAGMENTS HOISTED TO REGS
// (loaded once from smem after stage 0 lands; no Q ldmatrix in the mainloop).
// ---------------------------------------------------------------------------
#define KVSTG 32768

__global__ void __launch_bounds__(128) attn_mma()
{
    extern __shared__ char axm[];
    const uint32_t smb = smem_u32(axm);
    const int tid = threadIdx.x, lane = tid & 31, wid = tid >> 5;
    const int bh = blockIdx.y, q0 = blockIdx.x * 128;
    const int wq = wid * 32;

    const size_t gbase = (size_t)bh * SEQ * HD;
    const __nv_bfloat16* pQh = g_qh + gbase + (size_t)q0 * HD;
    const __nv_bfloat16* pQl = g_ql + gbase + (size_t)q0 * HD;

#pragma unroll
    for (int i = 0; i < 8; i++) {
        int idx = tid + i * 128;
        int r = idx >> 3, seg = idx & 7;
        const uint32_t so = sw128(r * 128 + seg * 16);
        CP16(smb + so,         pQh + (size_t)r * HD + seg * 8);
        CP16(smb + 16384 + so, pQl + (size_t)r * HD + seg * 8);
    }

    const __nv_bfloat16* gkv[4] = {g_kh + gbase, g_kl + gbase,
                                   g_vh + gbase, g_vl + gbase};
    auto load_kv = [&](int s, int it) {
        const uint32_t base = smb + 32768 + s * KVSTG;
#pragma unroll
        for (int sel = 0; sel < 4; sel++) {
            const __nv_bfloat16* g = gkv[sel] + (size_t)it * 64 * HD;
#pragma unroll
            for (int i = 0; i < 4; i++) {
                int idx = tid + i * 128;
                int r = idx >> 3, seg = idx & 7;
                CP16(base + sel * 8192 + sw128(r * 128 + seg * 16),
                     g + (size_t)r * HD + seg * 8);
            }
        }
        CP_COMMIT();
    };
    load_kv(0, 0);
    load_kv(1, 1);

    const int a_row = wq + (lane & 15);
    const int a_kb  = (lane >> 4) * 16;
    const int b_row = (lane & 7) + ((lane >> 4) << 3);
    const int b_kb  = ((lane >> 3) & 1) * 16;
    const int v_row = (lane & 7) + (((lane >> 3) & 1) << 3);
    const int v_cb  = (lane >> 4) * 16;

    // hoisted Q fragments: [ks][mt][4] hi + lo (64 regs)
    uint32_t qfh[4][2][4], qfl[4][2][4];

    float sO[2][8][4];
#pragma unroll
    for (int mt = 0; mt < 2; mt++)
#pragma unroll
        for (int nt = 0; nt < 8; nt++)
#pragma unroll
            for (int j = 0; j < 4; j++) sO[mt][nt][j] = 0.f;
    float m_i[4] = {-1e30f, -1e30f, -1e30f, -1e30f};
    float l_i[4] = {0.f, 0.f, 0.f, 0.f};

    for (int it = 0; it < SEQ / 64; it++) {
        const int s = it & 1;
        if (it == SEQ / 64 - 1) { CP_WAIT0(); } else { CP_WAIT1(); }
        __syncthreads();

        if (it == 0) {
            // Q arrived with stage 0 — load all Q fragments once.
#pragma unroll
            for (int ks = 0; ks < 4; ks++)
#pragma unroll
                for (int mt = 0; mt < 2; mt++) {
                    const uint32_t aoff =
                        sw128((a_row + mt * 16) * 128 + a_kb + ks * 32);
                    ldm_x4(qfh[ks][mt], smb + aoff);
                    ldm_x4(qfl[ks][mt], smb + 16384 + aoff);
                }
        }

        const uint32_t bKh = smb + 32768 + s * KVSTG;
        const uint32_t bKl = bKh + 8192;
        const uint32_t bVh = bKh + 16384;
        const uint32_t bVl = bKh + 24576;

        float sS[2][8][4];
#pragma unroll
        for (int mt = 0; mt < 2; mt++)
#pragma unroll
            for (int nt = 0; nt < 8; nt++)
#pragma unroll
                for (int j = 0; j < 4; j++) sS[mt][nt][j] = 0.f;

#pragma unroll
        for (int ks = 0; ks < 4; ks++) {
#pragma unroll
            for (int ng = 0; ng < 4; ng++) {
                uint32_t kh[4], kl[4];
                const uint32_t off = sw128((ng * 16 + b_row) * 128 + b_kb + ks * 32);
                ldm_x4(kh, bKh + off);
                ldm_x4(kl, bKl + off);
#pragma unroll
                for (int mt = 0; mt < 2; mt++) {
                    mma_bf16(sS[mt][2*ng],   qfh[ks][mt], &kh[0]);
                    mma_bf16(sS[mt][2*ng],   qfh[ks][mt], &kl[0]);
                    mma_bf16(sS[mt][2*ng],   qfl[ks][mt], &kh[0]);
                    mma_bf16(sS[mt][2*ng+1], qfh[ks][mt], &kh[2]);
                    mma_bf16(sS[mt][2*ng+1], qfh[ks][mt], &kl[2]);
                    mma_bf16(sS[mt][2*ng+1], qfl[ks][mt], &kh[2]);
                }
            }
        }

#pragma unroll
        for (int mt = 0; mt < 2; mt++) {
            float mx0 = -1e30f, mx1 = -1e30f;
#pragma unroll
            for (int nt = 0; nt < 8; nt++) {
                mx0 = fmaxf(mx0, fmaxf(sS[mt][nt][0], sS[mt][nt][1]));
                mx1 = fmaxf(mx1, fmaxf(sS[mt][nt][2], sS[mt][nt][3]));
            }
            mx0 = fmaxf(mx0, __shfl_xor_sync(0xffffffffu, mx0, 1));
            mx0 = fmaxf(mx0, __shfl_xor_sync(0xffffffffu, mx0, 2));
            mx1 = fmaxf(mx1, __shfl_xor_sync(0xffffffffu, mx1, 1));
            mx1 = fmaxf(mx1, __shfl_xor_sync(0xffffffffu, mx1, 2));
            const float mn0 = fmaxf(m_i[mt*2],   mx0);
            const float mn1 = fmaxf(m_i[mt*2+1], mx1);
            const float al0 = __expf(m_i[mt*2]   - mn0);
            const float al1 = __expf(m_i[mt*2+1] - mn1);
            float rs0 = 0.f, rs1 = 0.f;
#pragma unroll
            for (int nt = 0; nt < 8; nt++) {
                sS[mt][nt][0] = __expf(sS[mt][nt][0] - mn0);
                sS[mt][nt][1] = __expf(sS[mt][nt][1] - mn0);
                sS[mt][nt][2] = __expf(sS[mt][nt][2] - mn1);
                sS[mt][nt][3] = __expf(sS[mt][nt][3] - mn1);
                rs0 += sS[mt][nt][0] + sS[mt][nt][1];
                rs1 += sS[mt][nt][2] + sS[mt][nt][3];
            }
            rs0 += __shfl_xor_sync(0xffffffffu, rs0, 1);
            rs0 += __shfl_xor_sync(0xffffffffu, rs0, 2);
            rs1 += __shfl_xor_sync(0xffffffffu, rs1, 1);
            rs1 += __shfl_xor_sync(0xffffffffu, rs1, 2);
            l_i[mt*2]   = l_i[mt*2]   * al0 + rs0;  m_i[mt*2]   = mn0;
            l_i[mt*2+1] = l_i[mt*2+1] * al1 + rs1;  m_i[mt*2+1] = mn1;
#pragma unroll
            for (int nt = 0; nt < 8; nt++) {
                sO[mt][nt][0] *= al0; sO[mt][nt][1] *= al0;
                sO[mt][nt][2] *= al1; sO[mt][nt][3] *= al1;
            }
        }

#pragma unroll
        for (int ks = 0; ks < 4; ks++) {
            uint32_t ph[2][4], pl[2][4];
#pragma unroll
            for (int mt = 0; mt < 2; mt++) {
                const float* t0 = sS[mt][2 * ks];
                const float* t1 = sS[mt][2 * ks + 1];
                const float src[8] = {t0[0], t0[1], t0[2], t0[3],
                                      t1[0], t1[1], t1[2], t1[3]};
#pragma unroll
                for (int j = 0; j < 4; j++) {
                    const float p0 = src[j * 2], p1 = src[j * 2 + 1];
                    const uint32_t hp = cvt2(p1, p0);
                    ph[mt][j] = hp;
                    const float f0 = __uint_as_float(hp << 16);
                    const float f1 = __uint_as_float(hp & 0xffff0000u);
                    pl[mt][j] = cvt2(p1 - f1, p0 - f0);
                }
            }
#pragma unroll
            for (int dg = 0; dg < 4; dg++) {
                uint32_t vh[4], vl[4];
                const uint32_t off = sw128((ks * 16 + v_row) * 128 + dg * 32 + v_cb);
                ldm_x4t(vh, bVh + off);
                ldm_x4t(vl, bVl + off);
#pragma unroll
                for (int mt = 0; mt < 2; mt++) {
                    mma_bf16(sO[mt][2*dg],   ph[mt], &vh[0]);
                    mma_bf16(sO[mt][2*dg],   ph[mt], &vl[0]);
                    mma_bf16(sO[mt][2*dg],   pl[mt], &vh[0]);
                    mma_bf16(sO[mt][2*dg+1], ph[mt], &vh[2]);
                    mma_bf16(sO[mt][2*dg+1], ph[mt], &vl[2]);
                    mma_bf16(sO[mt][2*dg+1], pl[mt], &vh[2]);
                }
            }
        }

        __syncthreads();
        if (it + 2 < SEQ / 64) load_kv(s, it + 2);
    }

    const int b = bh >> 4, h = bh & 15;
    const int dc = (lane & 3) * 2;
#pragma unroll
    for (int mt = 0; mt < 2; mt++) {
        const float inv0 = 1.f / l_i[mt*2], inv1 = 1.f / l_i[mt*2+1];
        const int qr = q0 + wq + mt * 16 + (lane >> 2);
        const size_t base0 = ((size_t)b * SEQ + qr) * DM + h * HD + dc;
        const size_t base1 = base0 + (size_t)8 * DM;
#pragma unroll
        for (int nt = 0; nt < 8; nt++) {
            const float v0 = sO[mt][nt][0] * inv0, v1 = sO[mt][nt][1] * inv0;
            const float v2 = sO[mt][nt][2] * inv1, v3 = sO[mt][nt][3] * inv1;
            uint32_t h01 = cvt2(v1, v0);
            uint32_t l01 = cvt2(v1 - __uint_as_float(h01 & 0xffff0000u),
                                v0 - __uint_as_float(h01 << 16));
            uint32_t h23 = cvt2(v3, v2);
            uint32_t l23 = cvt2(v3 - __uint_as_float(h23 & 0xffff0000u),
                                v2 - __uint_as_float(h23 << 16));
            *(uint32_t*)&g_ah[base0 + nt * 8] = h01;
            *(uint32_t*)&g_al[base0 + nt * 8] = l01;
            *(uint32_t*)&g_ah[base1 + nt * 8] = h23;
            *(uint32_t*)&g_al[base1 + nt * 8] = l23;
        }
    }
}

// ---------------------------------------------------------------------------
extern "C" void kernel_launch(void* const* d_in, const int* in_sizes, int n_in,
                              void* d_out, int out_size)
{
    const float* x      = (const float*)d_in[0];
    const float* qkv_w  = (const float*)d_in[1];
    const float* qkv_b  = (const float*)d_in[2];
    const float* proj_w = (const float*)d_in[3];
    const float* proj_b = (const float*)d_in[4];
    float* out = (float*)d_out;

    void *xh, *xl, *wh, *wl, *pwh, *pwl, *ah, *al;
    cudaGetSymbolAddress(&xh, g_xh);   cudaGetSymbolAddress(&xl, g_xl);
    cudaGetSymbolAddress(&wh, g_wh);   cudaGetSymbolAddress(&wl, g_wl);
    cudaGetSymbolAddress(&pwh, g_pwh); cudaGetSymbolAddress(&pwl, g_pwl);
    cudaGetSymbolAddress(&ah, g_ah);   cudaGetSymbolAddress(&al, g_al);

    cudaFuncSetAttribute(gemm_qkv, cudaFuncAttributeMaxDynamicSharedMemorySize,
                         2 * GSTG);
    cudaFuncSetAttribute(gemm_qkv, cudaFuncAttributePreferredSharedMemoryCarveout,
                         100);
    cudaFuncSetAttribute(gemm_proj, cudaFuncAttributeMaxDynamicSharedMemorySize,
                         2 * STAGE_B);
    const int asmem = 32768 + 2 * KVSTG;           // 98304
    cudaFuncSetAttribute(attn_mma, cudaFuncAttributeMaxDynamicSharedMemorySize,
                         asmem);

    split_all<<<8192, 256>>>(x, qkv_w, proj_w);
    gemm_qkv<<<dim3(32, MROWS / 128), dim3(128), 2 * GSTG>>>(
        (const __nv_bfloat16*)xh, (const __nv_bfloat16*)xl,
        (const __nv_bfloat16*)wh, (const __nv_bfloat16*)wl, qkv_b);
    attn_mma<<<dim3(SEQ / 128, NB * NH), dim3(128), asmem>>>();
    gemm_proj<<<dim3(DM / 256, MROWS / 128), dim3(256), 2 * STAGE_B>>>(
        (const __nv_bfloat16*)ah, (const __nv_bfloat16*)al,
        (const __nv_bfloat16*)pwh, (const __nv_bfloat16*)pwl,
        proj_b, out);
}

// round 16
// speedup vs baseline: 1.0645x; 1.0645x over previous
#include <cuda_runtime.h>
#include <cuda_bf16.h>
#include <cstdint>

#define SEQ  2048
#define DM   1024
#define NH   16
#define HD   64
#define NB   2
#define MROWS (NB*SEQ)

// ---------------- scratch (device globals; no allocation allowed) ----------
#define NX   ((size_t)MROWS*DM)
#define NW   ((size_t)3*DM*DM)
#define NPW  ((size_t)DM*DM)
#define NQKV ((size_t)NB*NH*SEQ*HD)

__device__ __nv_bfloat16 g_xh[NX],  g_xl[NX];
__device__ __nv_bfloat16 g_wh[NW],  g_wl[NW];
__device__ float g_pwt[NPW];          // proj_w, tf32-rounded fp32
__device__ float g_attn[NX];          // attention output, tf32-rounded fp32
__device__ __nv_bfloat16 g_qh[NQKV], g_ql[NQKV];
__device__ __nv_bfloat16 g_kh[NQKV], g_kl[NQKV];
__device__ __nv_bfloat16 g_vh[NQKV], g_vl[NQKV];

// ---------------- PTX helpers ----------------------------------------------
__device__ __forceinline__ uint32_t smem_u32(const void* p) {
    uint32_t a;
    asm("{ .reg .u64 t; cvta.to.shared.u64 t, %1; cvt.u32.u64 %0, t; }"
        : "=r"(a) : "l"(p));
    return a;
}
#define CP16(s, g) \
    asm volatile("cp.async.cg.shared.global [%0], [%1], 16;" :: "r"(s), "l"(g))
#define CP_COMMIT() asm volatile("cp.async.commit_group;" ::: "memory")
#define CP_WAIT1()  asm volatile("cp.async.wait_group 1;" ::: "memory")
#define CP_WAIT0()  asm volatile("cp.async.wait_group 0;" ::: "memory")

__device__ __forceinline__ uint32_t sw128(uint32_t off) {
    return off ^ ((off >> 3) & 0x70);
}
__device__ __forceinline__ void ldm_x4(uint32_t* r, uint32_t a) {
    asm("ldmatrix.sync.aligned.m8n8.x4.shared.b16 {%0,%1,%2,%3}, [%4];"
        : "=r"(r[0]), "=r"(r[1]), "=r"(r[2]), "=r"(r[3]) : "r"(a));
}
__device__ __forceinline__ void ldm_x4t(uint32_t* r, uint32_t a) {
    asm("ldmatrix.sync.aligned.m8n8.x4.trans.shared.b16 {%0,%1,%2,%3}, [%4];"
        : "=r"(r[0]), "=r"(r[1]), "=r"(r[2]), "=r"(r[3]) : "r"(a));
}
__device__ __forceinline__ void mma_bf16(float* c, const uint32_t* a,
                                         const uint32_t* b) {
    asm("mma.sync.aligned.m16n8k16.row.col.f32.bf16.bf16.f32 "
        "{%0,%1,%2,%3}, {%4,%5,%6,%7}, {%8,%9}, {%0,%1,%2,%3};"
        : "+f"(c[0]), "+f"(c[1]), "+f"(c[2]), "+f"(c[3])
        : "r"(a[0]), "r"(a[1]), "r"(a[2]), "r"(a[3]), "r"(b[0]), "r"(b[1]));
}
__device__ __forceinline__ void mma_tf32(float* c, const uint32_t* a,
                                         const uint32_t* b) {
    asm("mma.sync.aligned.m16n8k8.row.col.f32.tf32.tf32.f32 "
        "{%0,%1,%2,%3}, {%4,%5,%6,%7}, {%8,%9}, {%0,%1,%2,%3};"
        : "+f"(c[0]), "+f"(c[1]), "+f"(c[2]), "+f"(c[3])
        : "r"(a[0]), "r"(a[1]), "r"(a[2]), "r"(a[3]), "r"(b[0]), "r"(b[1]));
}
__device__ __forceinline__ uint32_t cvt2(float hi, float lo) {
    uint32_t r;
    asm("cvt.rn.bf16x2.f32 %0, %1, %2;" : "=r"(r) : "f"(hi), "f"(lo));
    return r;
}
// tf32 round-to-nearest-even via bit trick (no PTX modifier risk)
__device__ __forceinline__ float tf32r(float f) {
    uint32_t u = __float_as_uint(f);
    u = (u + 0x00000fffu + ((u >> 13) & 1u)) & 0xffffe000u;
    return __uint_as_float(u);
}

// ---------------- fused preprocessing: x,w -> bf16 hi/lo; pw -> tf32 -------
__global__ void __launch_bounds__(256)
split_all(const float* __restrict__ x, const float* __restrict__ w,
          const float* __restrict__ pw)
{
    const size_t i = ((size_t)blockIdx.x * 256 + threadIdx.x) * 4;
    if (i >= NX + NW) {                      // proj_w: tf32 rounding copy
        const size_t off = i - NX - NW;
        float4 v = *(const float4*)(pw + off);
        float4 o;
        o.x = tf32r(v.x); o.y = tf32r(v.y);
        o.z = tf32r(v.z); o.w = tf32r(v.w);
        *(float4*)(g_pwt + off) = o;
        return;
    }
    const float* src;
    __nv_bfloat16 *hi, *lo;
    size_t off;
    if (i < NX) { src = x; hi = g_xh; lo = g_xl; off = i; }
    else        { src = w; hi = g_wh; lo = g_wl; off = i - NX; }
    float4 v = *(const float4*)(src + off);
    float f[4] = {v.x, v.y, v.z, v.w};
    __nv_bfloat16 h4[4], l4[4];
#pragma unroll
    for (int j = 0; j < 4; j++) {
        h4[j] = __float2bfloat16(f[j]);
        l4[j] = __float2bfloat16(f[j] - __bfloat162float(h4[j]));
    }
    *(uint2*)(hi + off) = *(uint2*)h4;
    *(uint2*)(lo + off) = *(uint2*)l4;
}

// ---------------------------------------------------------------------------
// QKV GEMM (round-12 winner): CTA 128x96, 128 thr (2m x 2n warps), warp 64x48,
// BK=32, 2-stage (56 KB), carveout 100.
// ---------------------------------------------------------------------------
#define GSTG 28672   // A 16KB + W 12KB

__global__ void __launch_bounds__(128, 3)
gemm_qkv(const __nv_bfloat16* __restrict__ Ah, const __nv_bfloat16* __restrict__ Al,
         const __nv_bfloat16* __restrict__ Wh, const __nv_bfloat16* __restrict__ Wl,
         const float* __restrict__ bias)
{
    constexpr int K = 1024, KT = K / 32;
    extern __shared__ char dsm[];
    const uint32_t smb = smem_u32(dsm);

    const int tid = threadIdx.x, lane = tid & 31, wid = tid >> 5;
    const int wm = wid & 1, wn = wid >> 1;
    const int bn = blockIdx.x * 96, bm = blockIdx.y * 128;

    auto load_stage = [&](int s, int kt) {
        const uint32_t base = smb + s * GSTG;
#pragma unroll
        for (int i = 0; i < 8; i++) {
            int idx = tid + i * 128;
            int r = idx >> 3, c = idx & 7;
            const __nv_bfloat16* g = ((c < 4) ? Ah : Al)
                + (size_t)(bm + r) * K + kt * 32 + (c & 3) * 8;
            CP16(base + sw128(r * 128 + c * 16), g);
        }
#pragma unroll
        for (int i = 0; i < 6; i++) {
            int idx = tid + i * 128;
            int r = idx >> 3, c = idx & 7;
            const __nv_bfloat16* g = ((c < 4) ? Wh : Wl)
                + (size_t)(bn + r) * K + kt * 32 + (c & 3) * 8;
            CP16(base + 16384 + sw128(r * 128 + c * 16), g);
        }
        CP_COMMIT();
    };

    float acc[4][6][4];
#pragma unroll
    for (int mt = 0; mt < 4; mt++)
#pragma unroll
        for (int nt = 0; nt < 6; nt++)
#pragma unroll
            for (int j = 0; j < 4; j++) acc[mt][nt][j] = 0.f;

    const int a_row = wm * 64 + (lane & 15);
    const int a_kb  = (lane >> 4) * 16;
    const int b_row = wn * 48 + (lane & 7) + ((lane >> 4) << 3);
    const int b_kb  = ((lane >> 3) & 1) * 16;

    load_stage(0, 0);
    load_stage(1, 1);

    for (int t = 0; t < KT; t++) {
        const int s = t & 1;
        if (t == KT - 1) { CP_WAIT0(); } else { CP_WAIT1(); }
        __syncthreads();

        const uint32_t bA = smb + s * GSTG;
        const uint32_t bW = bA + 16384;
#pragma unroll
        for (int ks = 0; ks < 2; ks++) {
            uint32_t afh[4][4], afl[4][4];
#pragma unroll
            for (int mt = 0; mt < 4; mt++) {
                const uint32_t off = (a_row + mt * 16) * 128 + a_kb + ks * 32;
                ldm_x4(afh[mt], bA + sw128(off));
                ldm_x4(afl[mt], bA + sw128(off + 64));
            }
#pragma unroll
            for (int ng = 0; ng < 3; ng++) {
                uint32_t bfh[4], bfl[4];
                const uint32_t off = (b_row + ng * 16) * 128 + b_kb + ks * 32;
                ldm_x4(bfh, bW + sw128(off));
                ldm_x4(bfl, bW + sw128(off + 64));
#pragma unroll
                for (int mt = 0; mt < 4; mt++) {
                    mma_bf16(acc[mt][2*ng],   afh[mt], &bfh[0]);
                    mma_bf16(acc[mt][2*ng],   afh[mt], &bfl[0]);
                    mma_bf16(acc[mt][2*ng],   afl[mt], &bfh[0]);
                    mma_bf16(acc[mt][2*ng+1], afh[mt], &bfh[2]);
                    mma_bf16(acc[mt][2*ng+1], afh[mt], &bfl[2]);
                    mma_bf16(acc[mt][2*ng+1], afl[mt], &bfh[2]);
                }
            }
        }
        __syncthreads();
        if (t + 2 < KT) load_stage(s, t + 2);
    }

    const int gr = lane >> 2, gc = (lane & 3) * 2;
#pragma unroll
    for (int mt = 0; mt < 4; mt++) {
#pragma unroll
        for (int half = 0; half < 2; half++) {
            const int m = bm + wm * 64 + mt * 16 + gr + half * 8;
#pragma unroll
            for (int nt = 0; nt < 6; nt++) {
                const int n = bn + wn * 48 + nt * 8 + gc;
                float vx = acc[mt][nt][half * 2 + 0] + __ldg(bias + n);
                float vy = acc[mt][nt][half * 2 + 1] + __ldg(bias + n + 1);
                const int chunk = n >> 10, rem = n & 1023;
                const int h = rem >> 6, d = rem & 63;
                const int b = m >> 11, tt = m & 2047;
                if (chunk == 0) { vx *= 0.125f; vy *= 0.125f; }
                __nv_bfloat16 hx = __float2bfloat16(vx);
                __nv_bfloat16 hy = __float2bfloat16(vy);
                __nv_bfloat16 lx = __float2bfloat16(vx - __bfloat162float(hx));
                __nv_bfloat16 ly = __float2bfloat16(vy - __bfloat162float(hy));
                __nv_bfloat16* dh = (chunk == 0) ? g_qh : (chunk == 1) ? g_kh : g_vh;
                __nv_bfloat16* dl = (chunk == 0) ? g_ql : (chunk == 1) ? g_kl : g_vl;
                const size_t off = (((size_t)b * NH + h) * SEQ + tt) * HD + d;
                __nv_bfloat162 ph; ph.x = hx; ph.y = hy;
                __nv_bfloat162 pl; pl.x = lx; pl.y = ly;
                *(__nv_bfloat162*)&dh[off] = ph;
                *(__nv_bfloat162*)&dl[off] = pl;
            }
        }
    }
}

// ---------------------------------------------------------------------------
// Projection GEMM — tf32 single-pass. CTA 128x256, 8 warps (2m x 4n),
// warp tile 64x64, BK=32 fp32 (128B rows, SW128), 2-stage (96 KB).
// ---------------------------------------------------------------------------
#define PT_A 16384                 // 128 x 32 fp32
#define PT_W 32768                 // 256 x 32 fp32
#define PSTG (PT_A + PT_W)         // 49152

__global__ void __launch_bounds__(256)
gemm_proj(const float* __restrict__ A, const float* __restrict__ W,
          const float* __restrict__ bias, float* __restrict__ C)
{
    constexpr int K = 1024, KT = K / 32, N = DM;
    extern __shared__ char dsm[];
    const uint32_t smb = smem_u32(dsm);

    const int tid = threadIdx.x, lane = tid & 31, wid = tid >> 5;
    const int wm = wid & 1, wn = wid >> 1;
    const int bn = blockIdx.x * 256, bm = blockIdx.y * 128;

    auto load_stage = [&](int s, int kt) {
        const uint32_t base = smb + s * PSTG;
#pragma unroll
        for (int i = 0; i < 4; i++) {              // A: 128 rows x 128B
            int idx = tid + i * 256;
            int r = idx >> 3, c = idx & 7;
            CP16(base + sw128(r * 128 + c * 16),
                 A + (size_t)(bm + r) * K + kt * 32 + c * 4);
        }
#pragma unroll
        for (int i = 0; i < 8; i++) {              // W: 256 rows x 128B
            int idx = tid + i * 256;
            int r = idx >> 3, c = idx & 7;
            CP16(base + PT_A + sw128(r * 128 + c * 16),
                 W + (size_t)(bn + r) * K + kt * 32 + c * 4);
        }
        CP_COMMIT();
    };

    float acc[4][8][4];
#pragma unroll
    for (int mt = 0; mt < 4; mt++)
#pragma unroll
        for (int nt = 0; nt < 8; nt++)
#pragma unroll
            for (int j = 0; j < 4; j++) acc[mt][nt][j] = 0.f;

    const int a_row = wm * 64 + (lane & 15);
    const int a_kb  = (lane >> 4) * 16;
    const int b_row = wn * 64 + (lane & 7) + ((lane >> 4) << 3);
    const int b_kb  = ((lane >> 3) & 1) * 16;

    load_stage(0, 0);
    load_stage(1, 1);

    for (int t = 0; t < KT; t++) {
        const int s = t & 1;
        if (t == KT - 1) { CP_WAIT0(); } else { CP_WAIT1(); }
        __syncthreads();

        const uint32_t bA = smb + s * PSTG;
        const uint32_t bW = bA + PT_A;
#pragma unroll
        for (int ks = 0; ks < 4; ks++) {           // 4 x k8
            uint32_t af[4][4];
#pragma unroll
            for (int mt = 0; mt < 4; mt++) {
                const uint32_t off = (a_row + mt * 16) * 128 + a_kb + ks * 32;
                ldm_x4(af[mt], bA + sw128(off));
            }
#pragma unroll
            for (int ng = 0; ng < 4; ng++) {
                uint32_t bf[4];
                const uint32_t off = (b_row + ng * 16) * 128 + b_kb + ks * 32;
                ldm_x4(bf, bW + sw128(off));
#pragma unroll
                for (int mt = 0; mt < 4; mt++) {
                    mma_tf32(acc[mt][2*ng],   af[mt], &bf[0]);
                    mma_tf32(acc[mt][2*ng+1], af[mt], &bf[2]);
                }
            }
        }
        __syncthreads();
        if (t + 2 < KT) load_stage(s, t + 2);
    }

    const int gr = lane >> 2, gc = (lane & 3) * 2;
#pragma unroll
    for (int mt = 0; mt < 4; mt++) {
#pragma unroll
        for (int half = 0; half < 2; half++) {
            const int m = bm + wm * 64 + mt * 16 + gr + half * 8;
#pragma unroll
            for (int nt = 0; nt < 8; nt++) {
                const int n = bn + wn * 64 + nt * 8 + gc;
                float2 v;
                v.x = acc[mt][nt][half * 2 + 0] + __ldg(bias + n);
                v.y = acc[mt][nt][half * 2 + 1] + __ldg(bias + n + 1);
                *(float2*)&C[(size_t)m * N + n] = v;
            }
        }
    }
}

// ---------------------------------------------------------------------------
// mma.sync flash attention (round-12 body); epilogue -> tf32-rounded fp32 g_attn.
// ---------------------------------------------------------------------------
#define KVSTG 32768

__global__ void __launch_bounds__(128) attn_mma()
{
    extern __shared__ char axm[];
    const uint32_t smb = smem_u32(axm);
    const int tid = threadIdx.x, lane = tid & 31, wid = tid >> 5;
    const int bh = blockIdx.y, q0 = blockIdx.x * 128;
    const int wq = wid * 32;

    const size_t gbase = (size_t)bh * SEQ * HD;
    const __nv_bfloat16* pQh = g_qh + gbase + (size_t)q0 * HD;
    const __nv_bfloat16* pQl = g_ql + gbase + (size_t)q0 * HD;

#pragma unroll
    for (int i = 0; i < 8; i++) {
        int idx = tid + i * 128;
        int r = idx >> 3, seg = idx & 7;
        const uint32_t so = sw128(r * 128 + seg * 16);
        CP16(smb + so,         pQh + (size_t)r * HD + seg * 8);
        CP16(smb + 16384 + so, pQl + (size_t)r * HD + seg * 8);
    }

    const __nv_bfloat16* gkv[4] = {g_kh + gbase, g_kl + gbase,
                                   g_vh + gbase, g_vl + gbase};
    auto load_kv = [&](int s, int it) {
        const uint32_t base = smb + 32768 + s * KVSTG;
#pragma unroll
        for (int sel = 0; sel < 4; sel++) {
            const __nv_bfloat16* g = gkv[sel] + (size_t)it * 64 * HD;
#pragma unroll
            for (int i = 0; i < 4; i++) {
                int idx = tid + i * 128;
                int r = idx >> 3, seg = idx & 7;
                CP16(base + sel * 8192 + sw128(r * 128 + seg * 16),
                     g + (size_t)r * HD + seg * 8);
            }
        }
        CP_COMMIT();
    };
    load_kv(0, 0);
    load_kv(1, 1);

    const int a_row = wq + (lane & 15);
    const int a_kb  = (lane >> 4) * 16;
    const int b_row = (lane & 7) + ((lane >> 4) << 3);
    const int b_kb  = ((lane >> 3) & 1) * 16;
    const int v_row = (lane & 7) + (((lane >> 3) & 1) << 3);
    const int v_cb  = (lane >> 4) * 16;

    float sO[2][8][4];
#pragma unroll
    for (int mt = 0; mt < 2; mt++)
#pragma unroll
        for (int nt = 0; nt < 8; nt++)
#pragma unroll
            for (int j = 0; j < 4; j++) sO[mt][nt][j] = 0.f;
    float m_i[4] = {-1e30f, -1e30f, -1e30f, -1e30f};
    float l_i[4] = {0.f, 0.f, 0.f, 0.f};

    for (int it = 0; it < SEQ / 64; it++) {
        const int s = it & 1;
        if (it == SEQ / 64 - 1) { CP_WAIT0(); } else { CP_WAIT1(); }
        __syncthreads();

        const uint32_t bKh = smb + 32768 + s * KVSTG;
        const uint32_t bKl = bKh + 8192;
        const uint32_t bVh = bKh + 16384;
        const uint32_t bVl = bKh + 24576;

        float sS[2][8][4];
#pragma unroll
        for (int mt = 0; mt < 2; mt++)
#pragma unroll
            for (int nt = 0; nt < 8; nt++)
#pragma unroll
                for (int j = 0; j < 4; j++) sS[mt][nt][j] = 0.f;

#pragma unroll
        for (int ks = 0; ks < 4; ks++) {
            uint32_t qh[2][4], ql[2][4];
#pragma unroll
            for (int mt = 0; mt < 2; mt++) {
                const uint32_t aoff = sw128((a_row + mt * 16) * 128 + a_kb + ks * 32);
                ldm_x4(qh[mt], smb + aoff);
                ldm_x4(ql[mt], smb + 16384 + aoff);
            }
#pragma unroll
            for (int ng = 0; ng < 4; ng++) {
                uint32_t kh[4], kl[4];
                const uint32_t off = sw128((ng * 16 + b_row) * 128 + b_kb + ks * 32);
                ldm_x4(kh, bKh + off);
                ldm_x4(kl, bKl + off);
#pragma unroll
                for (int mt = 0; mt < 2; mt++) {
                    mma_bf16(sS[mt][2*ng],   qh[mt], &kh[0]);
                    mma_bf16(sS[mt][2*ng],   qh[mt], &kl[0]);
                    mma_bf16(sS[mt][2*ng],   ql[mt], &kh[0]);
                    mma_bf16(sS[mt][2*ng+1], qh[mt], &kh[2]);
                    mma_bf16(sS[mt][2*ng+1], qh[mt], &kl[2]);
                    mma_bf16(sS[mt][2*ng+1], ql[mt], &kh[2]);
                }
            }
        }

#pragma unroll
        for (int mt = 0; mt < 2; mt++) {
            float mx0 = -1e30f, mx1 = -1e30f;
#pragma unroll
            for (int nt = 0; nt < 8; nt++) {
                mx0 = fmaxf(mx0, fmaxf(sS[mt][nt][0], sS[mt][nt][1]));
                mx1 = fmaxf(mx1, fmaxf(sS[mt][nt][2], sS[mt][nt][3]));
            }
            mx0 = fmaxf(mx0, __shfl_xor_sync(0xffffffffu, mx0, 1));
            mx0 = fmaxf(mx0, __shfl_xor_sync(0xffffffffu, mx0, 2));
            mx1 = fmaxf(mx1, __shfl_xor_sync(0xffffffffu, mx1, 1));
            mx1 = fmaxf(mx1, __shfl_xor_sync(0xffffffffu, mx1, 2));
            const float mn0 = fmaxf(m_i[mt*2],   mx0);
            const float mn1 = fmaxf(m_i[mt*2+1], mx1);
            const float al0 = __expf(m_i[mt*2]   - mn0);
            const float al1 = __expf(m_i[mt*2+1] - mn1);
            float rs0 = 0.f, rs1 = 0.f;
#pragma unroll
            for (int nt = 0; nt < 8; nt++) {
                sS[mt][nt][0] = __expf(sS[mt][nt][0] - mn0);
                sS[mt][nt][1] = __expf(sS[mt][nt][1] - mn0);
                sS[mt][nt][2] = __expf(sS[mt][nt][2] - mn1);
                sS[mt][nt][3] = __expf(sS[mt][nt][3] - mn1);
                rs0 += sS[mt][nt][0] + sS[mt][nt][1];
                rs1 += sS[mt][nt][2] + sS[mt][nt][3];
            }
            rs0 += __shfl_xor_sync(0xffffffffu, rs0, 1);
            rs0 += __shfl_xor_sync(0xffffffffu, rs0, 2);
            rs1 += __shfl_xor_sync(0xffffffffu, rs1, 1);
            rs1 += __shfl_xor_sync(0xffffffffu, rs1, 2);
            l_i[mt*2]   = l_i[mt*2]   * al0 + rs0;  m_i[mt*2]   = mn0;
            l_i[mt*2+1] = l_i[mt*2+1] * al1 + rs1;  m_i[mt*2+1] = mn1;
#pragma unroll
            for (int nt = 0; nt < 8; nt++) {
                sO[mt][nt][0] *= al0; sO[mt][nt][1] *= al0;
                sO[mt][nt][2] *= al1; sO[mt][nt][3] *= al1;
            }
        }

#pragma unroll
        for (int ks = 0; ks < 4; ks++) {
            uint32_t ph[2][4], pl[2][4];
#pragma unroll
            for (int mt = 0; mt < 2; mt++) {
                const float* t0 = sS[mt][2 * ks];
                const float* t1 = sS[mt][2 * ks + 1];
                const float src[8] = {t0[0], t0[1], t0[2], t0[3],
                                      t1[0], t1[1], t1[2], t1[3]};
#pragma unroll
                for (int j = 0; j < 4; j++) {
                    const float p0 = src[j * 2], p1 = src[j * 2 + 1];
                    const uint32_t hp = cvt2(p1, p0);
                    ph[mt][j] = hp;
                    const float f0 = __uint_as_float(hp << 16);
                    const float f1 = __uint_as_float(hp & 0xffff0000u);
                    pl[mt][j] = cvt2(p1 - f1, p0 - f0);
                }
            }
#pragma unroll
            for (int dg = 0; dg < 4; dg++) {
                uint32_t vh[4], vl[4];
                const uint32_t off = sw128((ks * 16 + v_row) * 128 + dg * 32 + v_cb);
                ldm_x4t(vh, bVh + off);
                ldm_x4t(vl, bVl + off);
#pragma unroll
                for (int mt = 0; mt < 2; mt++) {
                    mma_bf16(sO[mt][2*dg],   ph[mt], &vh[0]);
                    mma_bf16(sO[mt][2*dg],   ph[mt], &vl[0]);
                    mma_bf16(sO[mt][2*dg],   pl[mt], &vh[0]);
                    mma_bf16(sO[mt][2*dg+1], ph[mt], &vh[2]);
                    mma_bf16(sO[mt][2*dg+1], ph[mt], &vl[2]);
                    mma_bf16(sO[mt][2*dg+1], pl[mt], &vh[2]);
                }
            }
        }

        __syncthreads();
        if (it + 2 < SEQ / 64) load_kv(s, it + 2);
    }

    // epilogue: O/l -> tf32-rounded fp32 into g_attn ([B,N,H*hd])
    const int b = bh >> 4, h = bh & 15;
    const int dc = (lane & 3) * 2;
#pragma unroll
    for (int mt = 0; mt < 2; mt++) {
        const float inv0 = 1.f / l_i[mt*2], inv1 = 1.f / l_i[mt*2+1];
        const int qr = q0 + wq + mt * 16 + (lane >> 2);
        const size_t base0 = ((size_t)b * SEQ + qr) * DM + h * HD + dc;
        const size_t base1 = base0 + (size_t)8 * DM;
#pragma unroll
        for (int nt = 0; nt < 8; nt++) {
            float2 v01, v23;
            v01.x = tf32r(sO[mt][nt][0] * inv0);
            v01.y = tf32r(sO[mt][nt][1] * inv0);
            v23.x = tf32r(sO[mt][nt][2] * inv1);
            v23.y = tf32r(sO[mt][nt][3] * inv1);
            *(float2*)&g_attn[base0 + nt * 8] = v01;
            *(float2*)&g_attn[base1 + nt * 8] = v23;
        }
    }
}

// ---------------------------------------------------------------------------
extern "C" void kernel_launch(void* const* d_in, const int* in_sizes, int n_in,
                              void* d_out, int out_size)
{
    const float* x      = (const float*)d_in[0];
    const float* qkv_w  = (const float*)d_in[1];
    const float* qkv_b  = (const float*)d_in[2];
    const float* proj_w = (const float*)d_in[3];
    const float* proj_b = (const float*)d_in[4];
    float* out = (float*)d_out;

    void *xh, *xl, *wh, *wl, *pwt, *attn;
    cudaGetSymbolAddress(&xh, g_xh);   cudaGetSymbolAddress(&xl, g_xl);
    cudaGetSymbolAddress(&wh, g_wh);   cudaGetSymbolAddress(&wl, g_wl);
    cudaGetSymbolAddress(&pwt, g_pwt); cudaGetSymbolAddress(&attn, g_attn);

    cudaFuncSetAttribute(gemm_qkv, cudaFuncAttributeMaxDynamicSharedMemorySize,
                         2 * GSTG);
    cudaFuncSetAttribute(gemm_qkv, cudaFuncAttributePreferredSharedMemoryCarveout,
                         100);
    cudaFuncSetAttribute(gemm_proj, cudaFuncAttributeMaxDynamicSharedMemorySize,
                         2 * PSTG);
    const int asmem = 32768 + 2 * KVSTG;           // 98304
    cudaFuncSetAttribute(attn_mma, cudaFuncAttributeMaxDynamicSharedMemorySize,
                         asmem);

    split_all<<<8192, 256>>>(x, qkv_w, proj_w);
    gemm_qkv<<<dim3(32, MROWS / 128), dim3(128), 2 * GSTG>>>(
        (const __nv_bfloat16*)xh, (const __nv_bfloat16*)xl,
        (const __nv_bfloat16*)wh, (const __nv_bfloat16*)wl, qkv_b);
    attn_mma<<<dim3(SEQ / 128, NB * NH), dim3(128), asmem>>>();
    gemm_proj<<<dim3(DM / 256, MROWS / 128), dim3(256), 2 * PSTG>>>(
        (const float*)attn, (const float*)pwt, proj_b, out);
}

// round 17
// speedup vs baseline: 1.0956x; 1.0292x over previous
#include <cuda_runtime.h>
#include <cuda_bf16.h>
#include <cstdint>

#define SEQ  2048
#define DM   1024
#define NH   16
#define HD   64
#define NB   2
#define MROWS (NB*SEQ)

// ---------------- scratch (device globals; no allocation allowed) ----------
#define NX   ((size_t)MROWS*DM)
#define NW   ((size_t)3*DM*DM)
#define NPW  ((size_t)DM*DM)
#define NQKV ((size_t)NB*NH*SEQ*HD)

__device__ float g_xt[NX];            // x, tf32-rounded fp32
__device__ float g_wt[NW];            // qkv_w, tf32-rounded fp32
__device__ float g_pwt[NPW];          // proj_w, tf32-rounded fp32
__device__ float g_attn[NX];          // attention output, tf32-rounded fp32
__device__ __nv_bfloat16 g_qh[NQKV], g_ql[NQKV];
__device__ __nv_bfloat16 g_kh[NQKV], g_kl[NQKV];
__device__ __nv_bfloat16 g_vh[NQKV], g_vl[NQKV];

// ---------------- PTX helpers ----------------------------------------------
__device__ __forceinline__ uint32_t smem_u32(const void* p) {
    uint32_t a;
    asm("{ .reg .u64 t; cvta.to.shared.u64 t, %1; cvt.u32.u64 %0, t; }"
        : "=r"(a) : "l"(p));
    return a;
}
#define CP16(s, g) \
    asm volatile("cp.async.cg.shared.global [%0], [%1], 16;" :: "r"(s), "l"(g))
#define CP_COMMIT() asm volatile("cp.async.commit_group;" ::: "memory")
#define CP_WAIT1()  asm volatile("cp.async.wait_group 1;" ::: "memory")
#define CP_WAIT0()  asm volatile("cp.async.wait_group 0;" ::: "memory")

__device__ __forceinline__ uint32_t sw128(uint32_t off) {
    return off ^ ((off >> 3) & 0x70);
}
__device__ __forceinline__ void ldm_x4(uint32_t* r, uint32_t a) {
    asm("ldmatrix.sync.aligned.m8n8.x4.shared.b16 {%0,%1,%2,%3}, [%4];"
        : "=r"(r[0]), "=r"(r[1]), "=r"(r[2]), "=r"(r[3]) : "r"(a));
}
__device__ __forceinline__ void ldm_x4t(uint32_t* r, uint32_t a) {
    asm("ldmatrix.sync.aligned.m8n8.x4.trans.shared.b16 {%0,%1,%2,%3}, [%4];"
        : "=r"(r[0]), "=r"(r[1]), "=r"(r[2]), "=r"(r[3]) : "r"(a));
}
__device__ __forceinline__ void mma_bf16(float* c, const uint32_t* a,
                                         const uint32_t* b) {
    asm("mma.sync.aligned.m16n8k16.row.col.f32.bf16.bf16.f32 "
        "{%0,%1,%2,%3}, {%4,%5,%6,%7}, {%8,%9}, {%0,%1,%2,%3};"
        : "+f"(c[0]), "+f"(c[1]), "+f"(c[2]), "+f"(c[3])
        : "r"(a[0]), "r"(a[1]), "r"(a[2]), "r"(a[3]), "r"(b[0]), "r"(b[1]));
}
__device__ __forceinline__ void mma_tf32(float* c, const uint32_t* a,
                                         const uint32_t* b) {
    asm("mma.sync.aligned.m16n8k8.row.col.f32.tf32.tf32.f32 "
        "{%0,%1,%2,%3}, {%4,%5,%6,%7}, {%8,%9}, {%0,%1,%2,%3};"
        : "+f"(c[0]), "+f"(c[1]), "+f"(c[2]), "+f"(c[3])
        : "r"(a[0]), "r"(a[1]), "r"(a[2]), "r"(a[3]), "r"(b[0]), "r"(b[1]));
}
__device__ __forceinline__ uint32_t cvt2(float hi, float lo) {
    uint32_t r;
    asm("cvt.rn.bf16x2.f32 %0, %1, %2;" : "=r"(r) : "f"(hi), "f"(lo));
    return r;
}
// tf32 round-to-nearest-even via bit trick
__device__ __forceinline__ float tf32r(float f) {
    uint32_t u = __float_as_uint(f);
    u = (u + 0x00000fffu + ((u >> 13) & 1u)) & 0xffffe000u;
    return __uint_as_float(u);
}

// ---------------- preprocessing: x, qkv_w, proj_w -> tf32-rounded fp32 -----
__global__ void __launch_bounds__(256)
tf32_all(const float* __restrict__ x, const float* __restrict__ w,
         const float* __restrict__ pw)
{
    const size_t i = ((size_t)blockIdx.x * 256 + threadIdx.x) * 4;
    const float* src;
    float* dst;
    size_t off;
    if (i < NX)           { src = x;  dst = g_xt;  off = i; }
    else if (i < NX + NW) { src = w;  dst = g_wt;  off = i - NX; }
    else                  { src = pw; dst = g_pwt; off = i - NX - NW; }
    float4 v = *(const float4*)(src + off);
    float4 o;
    o.x = tf32r(v.x); o.y = tf32r(v.y);
    o.z = tf32r(v.z); o.w = tf32r(v.w);
    *(float4*)(dst + off) = o;
}

// ---------------------------------------------------------------------------
// QKV GEMM — tf32 single-pass. CTA 128x256, 8 warps (2m x 4n), warp 64x64,
// BK=32 fp32 (128B rows, SW128), 2-stage (96 KB).
// Epilogue: split + scatter into g_{q,k,v}{h,l} bf16 ([B,H,N,hd]), Q x0.125.
// ---------------------------------------------------------------------------
#define PT_A 16384                 // 128 x 32 fp32
#define PT_W 32768                 // 256 x 32 fp32
#define PSTG (PT_A + PT_W)         // 49152

__global__ void __launch_bounds__(256)
gemm_qkv(const float* __restrict__ A, const float* __restrict__ W,
         const float* __restrict__ bias)
{
    constexpr int K = 1024, KT = K / 32, N = 3 * DM;
    extern __shared__ char dsm[];
    const uint32_t smb = smem_u32(dsm);

    const int tid = threadIdx.x, lane = tid & 31, wid = tid >> 5;
    const int wm = wid & 1, wn = wid >> 1;
    const int bn = blockIdx.x * 256, bm = blockIdx.y * 128;

    auto load_stage = [&](int s, int kt) {
        const uint32_t base = smb + s * PSTG;
#pragma unroll
        for (int i = 0; i < 4; i++) {              // A: 128 rows x 128B
            int idx = tid + i * 256;
            int r = idx >> 3, c = idx & 7;
            CP16(base + sw128(r * 128 + c * 16),
                 A + (size_t)(bm + r) * K + kt * 32 + c * 4);
        }
#pragma unroll
        for (int i = 0; i < 8; i++) {              // W: 256 rows x 128B
            int idx = tid + i * 256;
            int r = idx >> 3, c = idx & 7;
            CP16(base + PT_A + sw128(r * 128 + c * 16),
                 W + (size_t)(bn + r) * K + kt * 32 + c * 4);
        }
        CP_COMMIT();
    };

    float acc[4][8][4];
#pragma unroll
    for (int mt = 0; mt < 4; mt++)
#pragma unroll
        for (int nt = 0; nt < 8; nt++)
#pragma unroll
            for (int j = 0; j < 4; j++) acc[mt][nt][j] = 0.f;

    const int a_row = wm * 64 + (lane & 15);
    const int a_kb  = (lane >> 4) * 16;
    const int b_row = wn * 64 + (lane & 7) + ((lane >> 4) << 3);
    const int b_kb  = ((lane >> 3) & 1) * 16;

    load_stage(0, 0);
    load_stage(1, 1);

    for (int t = 0; t < KT; t++) {
        const int s = t & 1;
        if (t == KT - 1) { CP_WAIT0(); } else { CP_WAIT1(); }
        __syncthreads();

        const uint32_t bA = smb + s * PSTG;
        const uint32_t bW = bA + PT_A;
#pragma unroll
        for (int ks = 0; ks < 4; ks++) {           // 4 x k8
            uint32_t af[4][4];
#pragma unroll
            for (int mt = 0; mt < 4; mt++) {
                const uint32_t off = (a_row + mt * 16) * 128 + a_kb + ks * 32;
                ldm_x4(af[mt], bA + sw128(off));
            }
#pragma unroll
            for (int ng = 0; ng < 4; ng++) {
                uint32_t bf[4];
                const uint32_t off = (b_row + ng * 16) * 128 + b_kb + ks * 32;
                ldm_x4(bf, bW + sw128(off));
#pragma unroll
                for (int mt = 0; mt < 4; mt++) {
                    mma_tf32(acc[mt][2*ng],   af[mt], &bf[0]);
                    mma_tf32(acc[mt][2*ng+1], af[mt], &bf[2]);
                }
            }
        }
        __syncthreads();
        if (t + 2 < KT) load_stage(s, t + 2);
    }

    const int gr = lane >> 2, gc = (lane & 3) * 2;
#pragma unroll
    for (int mt = 0; mt < 4; mt++) {
#pragma unroll
        for (int half = 0; half < 2; half++) {
            const int m = bm + wm * 64 + mt * 16 + gr + half * 8;
#pragma unroll
            for (int nt = 0; nt < 8; nt++) {
                const int n = bn + wn * 64 + nt * 8 + gc;
                float vx = acc[mt][nt][half * 2 + 0] + __ldg(bias + n);
                float vy = acc[mt][nt][half * 2 + 1] + __ldg(bias + n + 1);
                const int chunk = n >> 10, rem = n & 1023;
                const int h = rem >> 6, d = rem & 63;
                const int b = m >> 11, tt = m & 2047;
                if (chunk == 0) { vx *= 0.125f; vy *= 0.125f; }
                __nv_bfloat16 hx = __float2bfloat16(vx);
                __nv_bfloat16 hy = __float2bfloat16(vy);
                __nv_bfloat16 lx = __float2bfloat16(vx - __bfloat162float(hx));
                __nv_bfloat16 ly = __float2bfloat16(vy - __bfloat162float(hy));
                __nv_bfloat16* dh = (chunk == 0) ? g_qh : (chunk == 1) ? g_kh : g_vh;
                __nv_bfloat16* dl = (chunk == 0) ? g_ql : (chunk == 1) ? g_kl : g_vl;
                const size_t off = (((size_t)b * NH + h) * SEQ + tt) * HD + d;
                __nv_bfloat162 ph; ph.x = hx; ph.y = hy;
                __nv_bfloat162 pl; pl.x = lx; pl.y = ly;
                *(__nv_bfloat162*)&dh[off] = ph;
                *(__nv_bfloat162*)&dl[off] = pl;
            }
        }
    }
}

// ---------------------------------------------------------------------------
// Projection GEMM — tf32 single-pass (round-16 winner).
// ---------------------------------------------------------------------------
__global__ void __launch_bounds__(256)
gemm_proj(const float* __restrict__ A, const float* __restrict__ W,
          const float* __restrict__ bias, float* __restrict__ C)
{
    constexpr int K = 1024, KT = K / 32, N = DM;
    extern __shared__ char dsm[];
    const uint32_t smb = smem_u32(dsm);

    const int tid = threadIdx.x, lane = tid & 31, wid = tid >> 5;
    const int wm = wid & 1, wn = wid >> 1;
    const int bn = blockIdx.x * 256, bm = blockIdx.y * 128;

    auto load_stage = [&](int s, int kt) {
        const uint32_t base = smb + s * PSTG;
#pragma unroll
        for (int i = 0; i < 4; i++) {
            int idx = tid + i * 256;
            int r = idx >> 3, c = idx & 7;
            CP16(base + sw128(r * 128 + c * 16),
                 A + (size_t)(bm + r) * K + kt * 32 + c * 4);
        }
#pragma unroll
        for (int i = 0; i < 8; i++) {
            int idx = tid + i * 256;
            int r = idx >> 3, c = idx & 7;
            CP16(base + PT_A + sw128(r * 128 + c * 16),
                 W + (size_t)(bn + r) * K + kt * 32 + c * 4);
        }
        CP_COMMIT();
    };

    float acc[4][8][4];
#pragma unroll
    for (int mt = 0; mt < 4; mt++)
#pragma unroll
        for (int nt = 0; nt < 8; nt++)
#pragma unroll
            for (int j = 0; j < 4; j++) acc[mt][nt][j] = 0.f;

    const int a_row = wm * 64 + (lane & 15);
    const int a_kb  = (lane >> 4) * 16;
    const int b_row = wn * 64 + (lane & 7) + ((lane >> 4) << 3);
    const int b_kb  = ((lane >> 3) & 1) * 16;

    load_stage(0, 0);
    load_stage(1, 1);

    for (int t = 0; t < KT; t++) {
        const int s = t & 1;
        if (t == KT - 1) { CP_WAIT0(); } else { CP_WAIT1(); }
        __syncthreads();

        const uint32_t bA = smb + s * PSTG;
        const uint32_t bW = bA + PT_A;
#pragma unroll
        for (int ks = 0; ks < 4; ks++) {
            uint32_t af[4][4];
#pragma unroll
            for (int mt = 0; mt < 4; mt++) {
                const uint32_t off = (a_row + mt * 16) * 128 + a_kb + ks * 32;
                ldm_x4(af[mt], bA + sw128(off));
            }
#pragma unroll
            for (int ng = 0; ng < 4; ng++) {
                uint32_t bf[4];
                const uint32_t off = (b_row + ng * 16) * 128 + b_kb + ks * 32;
                ldm_x4(bf, bW + sw128(off));
#pragma unroll
                for (int mt = 0; mt < 4; mt++) {
                    mma_tf32(acc[mt][2*ng],   af[mt], &bf[0]);
                    mma_tf32(acc[mt][2*ng+1], af[mt], &bf[2]);
                }
            }
        }
        __syncthreads();
        if (t + 2 < KT) load_stage(s, t + 2);
    }

    const int gr = lane >> 2, gc = (lane & 3) * 2;
#pragma unroll
    for (int mt = 0; mt < 4; mt++) {
#pragma unroll
        for (int half = 0; half < 2; half++) {
            const int m = bm + wm * 64 + mt * 16 + gr + half * 8;
#pragma unroll
            for (int nt = 0; nt < 8; nt++) {
                const int n = bn + wn * 64 + nt * 8 + gc;
                float2 v;
                v.x = acc[mt][nt][half * 2 + 0] + __ldg(bias + n);
                v.y = acc[mt][nt][half * 2 + 1] + __ldg(bias + n + 1);
                *(float2*)&C[(size_t)m * N + n] = v;
            }
        }
    }
}

// ---------------------------------------------------------------------------
// mma.sync flash attention (round-12 body); epilogue -> tf32-rounded g_attn.
// ---------------------------------------------------------------------------
#define KVSTG 32768

__global__ void __launch_bounds__(128) attn_mma()
{
    extern __shared__ char axm[];
    const uint32_t smb = smem_u32(axm);
    const int tid = threadIdx.x, lane = tid & 31, wid = tid >> 5;
    const int bh = blockIdx.y, q0 = blockIdx.x * 128;
    const int wq = wid * 32;

    const size_t gbase = (size_t)bh * SEQ * HD;
    const __nv_bfloat16* pQh = g_qh + gbase + (size_t)q0 * HD;
    const __nv_bfloat16* pQl = g_ql + gbase + (size_t)q0 * HD;

#pragma unroll
    for (int i = 0; i < 8; i++) {
        int idx = tid + i * 128;
        int r = idx >> 3, seg = idx & 7;
        const uint32_t so = sw128(r * 128 + seg * 16);
        CP16(smb + so,         pQh + (size_t)r * HD + seg * 8);
        CP16(smb + 16384 + so, pQl + (size_t)r * HD + seg * 8);
    }

    const __nv_bfloat16* gkv[4] = {g_kh + gbase, g_kl + gbase,
                                   g_vh + gbase, g_vl + gbase};
    auto load_kv = [&](int s, int it) {
        const uint32_t base = smb + 32768 + s * KVSTG;
#pragma unroll
        for (int sel = 0; sel < 4; sel++) {
            const __nv_bfloat16* g = gkv[sel] + (size_t)it * 64 * HD;
#pragma unroll
            for (int i = 0; i < 4; i++) {
                int idx = tid + i * 128;
                int r = idx >> 3, seg = idx & 7;
                CP16(base + sel * 8192 + sw128(r * 128 + seg * 16),
                     g + (size_t)r * HD + seg * 8);
            }
        }
        CP_COMMIT();
    };
    load_kv(0, 0);
    load_kv(1, 1);

    const int a_row = wq + (lane & 15);
    const int a_kb  = (lane >> 4) * 16;
    const int b_row = (lane & 7) + ((lane >> 4) << 3);
    const int b_kb  = ((lane >> 3) & 1) * 16;
    const int v_row = (lane & 7) + (((lane >> 3) & 1) << 3);
    const int v_cb  = (lane >> 4) * 16;

    float sO[2][8][4];
#pragma unroll
    for (int mt = 0; mt < 2; mt++)
#pragma unroll
        for (int nt = 0; nt < 8; nt++)
#pragma unroll
            for (int j = 0; j < 4; j++) sO[mt][nt][j] = 0.f;
    float m_i[4] = {-1e30f, -1e30f, -1e30f, -1e30f};
    float l_i[4] = {0.f, 0.f, 0.f, 0.f};

    for (int it = 0; it < SEQ / 64; it++) {
        const int s = it & 1;
        if (it == SEQ / 64 - 1) { CP_WAIT0(); } else { CP_WAIT1(); }
        __syncthreads();

        const uint32_t bKh = smb + 32768 + s * KVSTG;
        const uint32_t bKl = bKh + 8192;
        const uint32_t bVh = bKh + 16384;
        const uint32_t bVl = bKh + 24576;

        float sS[2][8][4];
#pragma unroll
        for (int mt = 0; mt < 2; mt++)
#pragma unroll
            for (int nt = 0; nt < 8; nt++)
#pragma unroll
                for (int j = 0; j < 4; j++) sS[mt][nt][j] = 0.f;

#pragma unroll
        for (int ks = 0; ks < 4; ks++) {
            uint32_t qh[2][4], ql[2][4];
#pragma unroll
            for (int mt = 0; mt < 2; mt++) {
                const uint32_t aoff = sw128((a_row + mt * 16) * 128 + a_kb + ks * 32);
                ldm_x4(qh[mt], smb + aoff);
                ldm_x4(ql[mt], smb + 16384 + aoff);
            }
#pragma unroll
            for (int ng = 0; ng < 4; ng++) {
                uint32_t kh[4], kl[4];
                const uint32_t off = sw128((ng * 16 + b_row) * 128 + b_kb + ks * 32);
                ldm_x4(kh, bKh + off);
                ldm_x4(kl, bKl + off);
#pragma unroll
                for (int mt = 0; mt < 2; mt++) {
                    mma_bf16(sS[mt][2*ng],   qh[mt], &kh[0]);
                    mma_bf16(sS[mt][2*ng],   qh[mt], &kl[0]);
                    mma_bf16(sS[mt][2*ng],   ql[mt], &kh[0]);
                    mma_bf16(sS[mt][2*ng+1], qh[mt], &kh[2]);
                    mma_bf16(sS[mt][2*ng+1], qh[mt], &kl[2]);
                    mma_bf16(sS[mt][2*ng+1], ql[mt], &kh[2]);
                }
            }
        }

#pragma unroll
        for (int mt = 0; mt < 2; mt++) {
            float mx0 = -1e30f, mx1 = -1e30f;
#pragma unroll
            for (int nt = 0; nt < 8; nt++) {
                mx0 = fmaxf(mx0, fmaxf(sS[mt][nt][0], sS[mt][nt][1]));
                mx1 = fmaxf(mx1, fmaxf(sS[mt][nt][2], sS[mt][nt][3]));
            }
            mx0 = fmaxf(mx0, __shfl_xor_sync(0xffffffffu, mx0, 1));
            mx0 = fmaxf(mx0, __shfl_xor_sync(0xffffffffu, mx0, 2));
            mx1 = fmaxf(mx1, __shfl_xor_sync(0xffffffffu, mx1, 1));
            mx1 = fmaxf(mx1, __shfl_xor_sync(0xffffffffu, mx1, 2));
            const float mn0 = fmaxf(m_i[mt*2],   mx0);
            const float mn1 = fmaxf(m_i[mt*2+1], mx1);
            const float al0 = __expf(m_i[mt*2]   - mn0);
            const float al1 = __expf(m_i[mt*2+1] - mn1);
            float rs0 = 0.f, rs1 = 0.f;
#pragma unroll
            for (int nt = 0; nt < 8; nt++) {
                sS[mt][nt][0] = __expf(sS[mt][nt][0] - mn0);
                sS[mt][nt][1] = __expf(sS[mt][nt][1] - mn0);
                sS[mt][nt][2] = __expf(sS[mt][nt][2] - mn1);
                sS[mt][nt][3] = __expf(sS[mt][nt][3] - mn1);
                rs0 += sS[mt][nt][0] + sS[mt][nt][1];
                rs1 += sS[mt][nt][2] + sS[mt][nt][3];
            }
            rs0 += __shfl_xor_sync(0xffffffffu, rs0, 1);
            rs0 += __shfl_xor_sync(0xffffffffu, rs0, 2);
            rs1 += __shfl_xor_sync(0xffffffffu, rs1, 1);
            rs1 += __shfl_xor_sync(0xffffffffu, rs1, 2);
            l_i[mt*2]   = l_i[mt*2]   * al0 + rs0;  m_i[mt*2]   = mn0;
            l_i[mt*2+1] = l_i[mt*2+1] * al1 + rs1;  m_i[mt*2+1] = mn1;
#pragma unroll
            for (int nt = 0; nt < 8; nt++) {
                sO[mt][nt][0] *= al0; sO[mt][nt][1] *= al0;
                sO[mt][nt][2] *= al1; sO[mt][nt][3] *= al1;
            }
        }

#pragma unroll
        for (int ks = 0; ks < 4; ks++) {
            uint32_t ph[2][4], pl[2][4];
#pragma unroll
            for (int mt = 0; mt < 2; mt++) {
                const float* t0 = sS[mt][2 * ks];
                const float* t1 = sS[mt][2 * ks + 1];
                const float src[8] = {t0[0], t0[1], t0[2], t0[3],
                                      t1[0], t1[1], t1[2], t1[3]};
#pragma unroll
                for (int j = 0; j < 4; j++) {
                    const float p0 = src[j * 2], p1 = src[j * 2 + 1];
                    const uint32_t hp = cvt2(p1, p0);
                    ph[mt][j] = hp;
                    const float f0 = __uint_as_float(hp << 16);
                    const float f1 = __uint_as_float(hp & 0xffff0000u);
                    pl[mt][j] = cvt2(p1 - f1, p0 - f0);
                }
            }
#pragma unroll
            for (int dg = 0; dg < 4; dg++) {
                uint32_t vh[4], vl[4];
                const uint32_t off = sw128((ks * 16 + v_row) * 128 + dg * 32 + v_cb);
                ldm_x4t(vh, bVh + off);
                ldm_x4t(vl, bVl + off);
#pragma unroll
                for (int mt = 0; mt < 2; mt++) {
                    mma_bf16(sO[mt][2*dg],   ph[mt], &vh[0]);
                    mma_bf16(sO[mt][2*dg],   ph[mt], &vl[0]);
                    mma_bf16(sO[mt][2*dg],   pl[mt], &vh[0]);
                    mma_bf16(sO[mt][2*dg+1], ph[mt], &vh[2]);
                    mma_bf16(sO[mt][2*dg+1], ph[mt], &vl[2]);
                    mma_bf16(sO[mt][2*dg+1], pl[mt], &vh[2]);
                }
            }
        }

        __syncthreads();
        if (it + 2 < SEQ / 64) load_kv(s, it + 2);
    }

    // epilogue: O/l -> tf32-rounded fp32 into g_attn ([B,N,H*hd])
    const int b = bh >> 4, h = bh & 15;
    const int dc = (lane & 3) * 2;
#pragma unroll
    for (int mt = 0; mt < 2; mt++) {
        const float inv0 = 1.f / l_i[mt*2], inv1 = 1.f / l_i[mt*2+1];
        const int qr = q0 + wq + mt * 16 + (lane >> 2);
        const size_t base0 = ((size_t)b * SEQ + qr) * DM + h * HD + dc;
        const size_t base1 = base0 + (size_t)8 * DM;
#pragma unroll
        for (int nt = 0; nt < 8; nt++) {
            float2 v01, v23;
            v01.x = tf32r(sO[mt][nt][0] * inv0);
            v01.y = tf32r(sO[mt][nt][1] * inv0);
            v23.x = tf32r(sO[mt][nt][2] * inv1);
            v23.y = tf32r(sO[mt][nt][3] * inv1);
            *(float2*)&g_attn[base0 + nt * 8] = v01;
            *(float2*)&g_attn[base1 + nt * 8] = v23;
        }
    }
}

// ---------------------------------------------------------------------------
extern "C" void kernel_launch(void* const* d_in, const int* in_sizes, int n_in,
                              void* d_out, int out_size)
{
    const float* x      = (const float*)d_in[0];
    const float* qkv_w  = (const float*)d_in[1];
    const float* qkv_b  = (const float*)d_in[2];
    const float* proj_w = (const float*)d_in[3];
    const float* proj_b = (const float*)d_in[4];
    float* out = (float*)d_out;

    void *xt, *wt, *pwt, *attn;
    cudaGetSymbolAddress(&xt, g_xt);   cudaGetSymbolAddress(&wt, g_wt);
    cudaGetSymbolAddress(&pwt, g_pwt); cudaGetSymbolAddress(&attn, g_attn);

    cudaFuncSetAttribute(gemm_qkv, cudaFuncAttributeMaxDynamicSharedMemorySize,
                         2 * PSTG);
    cudaFuncSetAttribute(gemm_proj, cudaFuncAttributeMaxDynamicSharedMemorySize,
                         2 * PSTG);
    const int asmem = 32768 + 2 * KVSTG;           // 98304
    cudaFuncSetAttribute(attn_mma, cudaFuncAttributeMaxDynamicSharedMemorySize,
                         asmem);

    tf32_all<<<8192, 256>>>(x, qkv_w, proj_w);
    gemm_qkv<<<dim3(3 * DM / 256, MROWS / 128), dim3(256), 2 * PSTG>>>(
        (const float*)xt, (const float*)wt, qkv_b);
    attn_mma<<<dim3(SEQ / 128, NB * NH), dim3(128), asmem>>>();
    gemm_proj<<<dim3(DM / 256, MROWS / 128), dim3(256), 2 * PSTG>>>(
        (const float*)attn, (const float*)pwt, proj_b, out);
}